// round 17
// baseline (speedup 1.0000x reference)
#include <cuda_runtime.h>
#include <cuda_bf16.h>
#include <mma.h>
#include <cstdint>

using namespace nvcuda;

#define TBv 16
#define Nv  1024
#define Dv  512
#define Hv  8
#define HDv 64
#define Mv  (TBv * Nv)

__device__ __nv_bfloat16 gx_hi[(size_t)Mv * Dv], gx_lo[(size_t)Mv * Dv];
__device__ __nv_bfloat16 gw_hi[4 * Dv * Dv],     gw_lo[4 * Dv * Dv];
__device__ __nv_bfloat16 gq_hi[(size_t)Mv * Dv], gq_lo[(size_t)Mv * Dv];
__device__ __nv_bfloat16 gk_hi[(size_t)Mv * Dv], gk_lo[(size_t)Mv * Dv];
__device__ __nv_bfloat16 gv_hi[(size_t)Mv * Dv], gv_lo[(size_t)Mv * Dv];
__device__ __nv_bfloat16 gc_hi[(size_t)Mv * Dv], gc_lo[(size_t)Mv * Dv];

// ---- packed bf16x2 conversion helpers -------------------------------------
__device__ __forceinline__ uint32_t cvt_bf2(float x, float y) { // {lo=x, hi=y}
    uint32_t r;
    asm("cvt.rn.bf16x2.f32 %0, %1, %2;" : "=r"(r) : "f"(y), "f"(x));
    return r;
}
__device__ __forceinline__ float bflo_f(uint32_t p) { return __uint_as_float(p << 16); }
__device__ __forceinline__ float bfhi_f(uint32_t p) { return __uint_as_float(p & 0xffff0000u); }

__device__ __forceinline__ void split_store4(float4 v,
                                             __nv_bfloat16* __restrict__ hp,
                                             __nv_bfloat16* __restrict__ lp)
{
    uint32_t h01 = cvt_bf2(v.x, v.y);
    uint32_t h23 = cvt_bf2(v.z, v.w);
    ((uint32_t*)hp)[0] = h01;
    ((uint32_t*)hp)[1] = h23;
    ((uint32_t*)lp)[0] = cvt_bf2(v.x - bflo_f(h01), v.y - bfhi_f(h01));
    ((uint32_t*)lp)[1] = cvt_bf2(v.z - bflo_f(h23), v.w - bfhi_f(h23));
}
__device__ __forceinline__ void cp16(uint32_t dst, const void* src) {
    asm volatile("cp.async.cg.shared.global [%0], [%1], 16;" :: "r"(dst), "l"(src));
}
__device__ __forceinline__ void cp_commit() {
    asm volatile("cp.async.commit_group;" ::: "memory");
}
__device__ __forceinline__ void ldsm4(uint32_t (&r)[4], uint32_t a) {
    asm volatile("ldmatrix.sync.aligned.m8n8.x4.shared.b16 {%0,%1,%2,%3}, [%4];"
                 : "=r"(r[0]), "=r"(r[1]), "=r"(r[2]), "=r"(r[3]) : "r"(a));
}
__device__ __forceinline__ void ldsm4t(uint32_t (&r)[4], uint32_t a) {
    asm volatile("ldmatrix.sync.aligned.m8n8.x4.trans.shared.b16 {%0,%1,%2,%3}, [%4];"
                 : "=r"(r[0]), "=r"(r[1]), "=r"(r[2]), "=r"(r[3]) : "r"(a));
}
__device__ __forceinline__ void mma16816(float (&c)[4], const uint32_t (&a)[4],
                                         uint32_t b0, uint32_t b1) {
    asm volatile(
        "mma.sync.aligned.m16n8k16.row.col.f32.bf16.bf16.f32 "
        "{%0,%1,%2,%3}, {%4,%5,%6,%7}, {%8,%9}, {%0,%1,%2,%3};"
        : "+f"(c[0]), "+f"(c[1]), "+f"(c[2]), "+f"(c[3])
        : "r"(a[0]), "r"(a[1]), "r"(a[2]), "r"(a[3]), "r"(b0), "r"(b1));
}

using BFragA  = wmma::fragment<wmma::matrix_a, 16, 16, 16, __nv_bfloat16, wmma::row_major>;
using BFragBc = wmma::fragment<wmma::matrix_b, 16, 16, 16, __nv_bfloat16, wmma::col_major>;
using FragC   = wmma::fragment<wmma::accumulator, 16, 16, 16, float>;

// ---------------------------------------------------------------------------
#define NXf4 (Mv * Dv / 4)
#define NWf4 (Dv * Dv / 4)

__global__ __launch_bounds__(256) void split_kernel(
    const float* __restrict__ x,
    const float* __restrict__ wq, const float* __restrict__ wk,
    const float* __restrict__ wv, const float* __restrict__ wo)
{
    int i = blockIdx.x * 256 + threadIdx.x;
    const float* src; __nv_bfloat16 *dh, *dl; int j;
    if (i < NXf4) { src = x; j = i; dh = gx_hi; dl = gx_lo; }
    else {
        int r = i - NXf4;
        if (r >= 4 * NWf4) return;
        int sel = r / NWf4; j = r % NWf4;
        src = (sel == 0) ? wq : (sel == 1) ? wk : (sel == 2) ? wv : wo;
        dh = gw_hi + (size_t)sel * Dv * Dv;
        dl = gw_lo + (size_t)sel * Dv * Dv;
    }
    float4 v = ((const float4*)src)[j];
    split_store4(v, dh + 4 * (size_t)j, dl + 4 * (size_t)j);
}

// ===========================================================================
// Shared GEMM kstep (term-major)
// ===========================================================================
#define G_PLE  5120
#define G_PLB  10240

__device__ __forceinline__ void g_kstep(const char* smc, int ks,
                                        int wm, int wn, FragC (&acc)[4][2])
{
    const __nv_bfloat16* S = (const __nv_bfloat16*)smc;
    BFragA ahi[4], alo[4];
#pragma unroll
    for (int i = 0; i < 4; ++i) {
        wmma::load_matrix_sync(ahi[i], S + (wm + 16 * i) * 40 + ks * 16, 40);
        wmma::load_matrix_sync(alo[i], S + G_PLE + (wm + 16 * i) * 40 + ks * 16, 40);
    }
    BFragBc bhi[2], blo[2];
#pragma unroll
    for (int j = 0; j < 2; ++j) {
        wmma::load_matrix_sync(bhi[j], S + 2 * G_PLE + (wn + 16 * j) * 40 + ks * 16, 40);
        wmma::load_matrix_sync(blo[j], S + 3 * G_PLE + (wn + 16 * j) * 40 + ks * 16, 40);
    }
#pragma unroll
    for (int j = 0; j < 2; ++j)
#pragma unroll
        for (int i = 0; i < 4; ++i)
            wmma::mma_sync(acc[i][j], ahi[i], bhi[j], acc[i][j]);
#pragma unroll
    for (int j = 0; j < 2; ++j)
#pragma unroll
        for (int i = 0; i < 4; ++i)
            wmma::mma_sync(acc[i][j], ahi[i], blo[j], acc[i][j]);
#pragma unroll
    for (int j = 0; j < 2; ++j)
#pragma unroll
        for (int i = 0; i < 4; ++i)
            wmma::mma_sync(acc[i][j], alo[i], bhi[j], acc[i][j]);
}

// ---- qkv GEMM: reg-staged single-buffer schedule ---------------------------
#define G_BIAS 40960
#define GEMM_SMEM (40960 + 512)

__device__ __forceinline__ void gemm_single(
    const __nv_bfloat16* __restrict__ Ah, const __nv_bfloat16* __restrict__ Al,
    const __nv_bfloat16* __restrict__ Bh, const __nv_bfloat16* __restrict__ Bl,
    char* smc, FragC (&acc)[4][2])
{
    const int t = threadIdx.x;
    const int w = t >> 5;
    const int wm = (w & 1) * 64;
    const int wn = (w >> 1) * 32;
#pragma unroll
    for (int i = 0; i < 4; ++i)
#pragma unroll
        for (int j = 0; j < 2; ++j)
            wmma::fill_fragment(acc[i][j], 0.0f);

    for (int ch = 0; ch < 16; ++ch) {
        uint4 rg[8];
#pragma unroll
        for (int hh = 0; hh < 2; ++hh) {
            const int o = t + 256 * hh;
            const size_t off = (size_t)(o >> 2) * Dv + ch * 32 + (o & 3) * 8;
            rg[4 * hh + 0] = *(const uint4*)(Ah + off);
            rg[4 * hh + 1] = *(const uint4*)(Al + off);
            rg[4 * hh + 2] = *(const uint4*)(Bh + off);
            rg[4 * hh + 3] = *(const uint4*)(Bl + off);
        }
        __syncthreads();
#pragma unroll
        for (int hh = 0; hh < 2; ++hh) {
            const int o = t + 256 * hh;
            const int off = (o >> 2) * 80 + (o & 3) * 16;
            *(uint4*)(smc + off)             = rg[4 * hh + 0];
            *(uint4*)(smc + G_PLB + off)     = rg[4 * hh + 1];
            *(uint4*)(smc + 2 * G_PLB + off) = rg[4 * hh + 2];
            *(uint4*)(smc + 3 * G_PLB + off) = rg[4 * hh + 3];
        }
        __syncthreads();
        g_kstep(smc, 0, wm, wn, acc);
        g_kstep(smc, 1, wm, wn, acc);
    }
}

__global__ __launch_bounds__(256, 2) void qkv_gemm_p(
    const float* __restrict__ bq, const float* __restrict__ bk,
    const float* __restrict__ bv)
{
    extern __shared__ char smc[];
    const int t = threadIdx.x;
    const int m0   = blockIdx.x * 128;
    const int wsel = blockIdx.y >> 2;
    const int n0   = (blockIdx.y & 3) * 128;

    const float* bias = (wsel == 0) ? bq : (wsel == 1) ? bk : bv;
    __nv_bfloat16* oh = (wsel == 0) ? gq_hi : (wsel == 1) ? gk_hi : gv_hi;
    __nv_bfloat16* ol = (wsel == 0) ? gq_lo : (wsel == 1) ? gk_lo : gv_lo;

    float* biasS = (float*)(smc + G_BIAS);
    if (t < 128) biasS[t] = bias[n0 + t];

    FragC acc[4][2];
    gemm_single(gx_hi + (size_t)m0 * Dv, gx_lo + (size_t)m0 * Dv,
                gw_hi + (size_t)wsel * Dv * Dv + (size_t)n0 * Dv,
                gw_lo + (size_t)wsel * Dv * Dv + (size_t)n0 * Dv, smc, acc);

    float* Cs = (float*)smc;
    const int w = t >> 5, wn = (w >> 1) * 32;
    const int erow = t >> 2;
    const int ecol = (t & 3) * 32;
#pragma unroll
    for (int p = 0; p < 2; ++p) {
        __syncthreads();
        if ((w & 1) == p) {
#pragma unroll
            for (int i = 0; i < 4; ++i)
#pragma unroll
                for (int j = 0; j < 2; ++j)
                    wmma::store_matrix_sync(&Cs[(16 * i) * 132 + wn + 16 * j],
                                            acc[i][j], 132, wmma::mem_row_major);
        }
        __syncthreads();
        const int m  = m0 + p * 64 + erow;
        const int tb = m >> 10, n = m & 1023;
        const int h  = (n0 + ecol) >> 6;
        const int hd0 = (n0 + ecol) & 63;
        __nv_bfloat16* dh = oh + ((size_t)(tb * Hv + h) * Nv + n) * HDv + hd0;
        __nv_bfloat16* dl = ol + ((size_t)(tb * Hv + h) * Nv + n) * HDv + hd0;
#pragma unroll
        for (int c = 0; c < 32; c += 4) {
            float4 v = *(float4*)&Cs[erow * 132 + ecol + c];
            v.x += biasS[ecol + c + 0]; v.y += biasS[ecol + c + 1];
            v.z += biasS[ecol + c + 2]; v.w += biasS[ecol + c + 3];
            split_store4(v, dh + c, dl + c);
        }
    }
}

// ---- out GEMM: cp.async 2-stage pipeline -----------------------------------
#define G2_STG  40960
#define G2_BIAS 81920
#define GEMM2_SMEM (81920 + 512)

__device__ __forceinline__ void g2_prefetch(
    uint32_t sb, int stage,
    const __nv_bfloat16* __restrict__ Ah, const __nv_bfloat16* __restrict__ Al,
    const __nv_bfloat16* __restrict__ Bh, const __nv_bfloat16* __restrict__ Bl,
    int k0, int t)
{
    const __nv_bfloat16* pl[4] = {Ah, Al, Bh, Bl};
    const uint32_t base = sb + stage * G2_STG;
#pragma unroll
    for (int p = 0; p < 4; ++p) {
#pragma unroll
        for (int hh = 0; hh < 2; ++hh) {
            const int o = t + 256 * hh;
            const int row = o >> 2, seg = o & 3;
            cp16(base + p * G_PLB + row * 80 + seg * 16,
                 pl[p] + (size_t)row * Dv + k0 + seg * 8);
        }
    }
}

__global__ __launch_bounds__(256, 2) void out_gemm_p(
    const float* __restrict__ bo, float* __restrict__ out)
{
    extern __shared__ char smc[];
    const int t = threadIdx.x;
    const int m0 = blockIdx.x * 128;
    const int n0 = blockIdx.y * 128;
    const uint32_t sb = (uint32_t)__cvta_generic_to_shared(smc);

    float* biasS = (float*)(smc + G2_BIAS);
    if (t < 128) biasS[t] = bo[n0 + t];

    const __nv_bfloat16* Ah = gc_hi + (size_t)m0 * Dv;
    const __nv_bfloat16* Al = gc_lo + (size_t)m0 * Dv;
    const __nv_bfloat16* Bh = gw_hi + (size_t)3 * Dv * Dv + (size_t)n0 * Dv;
    const __nv_bfloat16* Bl = gw_lo + (size_t)3 * Dv * Dv + (size_t)n0 * Dv;

    const int w = t >> 5;
    const int wm = (w & 1) * 64;
    const int wn = (w >> 1) * 32;
    FragC acc[4][2];
#pragma unroll
    for (int i = 0; i < 4; ++i)
#pragma unroll
        for (int j = 0; j < 2; ++j)
            wmma::fill_fragment(acc[i][j], 0.0f);

    g2_prefetch(sb, 0, Ah, Al, Bh, Bl, 0, t);
    cp_commit();
    for (int ch = 0; ch < 16; ++ch) {
        if (ch < 15) {
            g2_prefetch(sb, (ch + 1) & 1, Ah, Al, Bh, Bl, (ch + 1) * 32, t);
            cp_commit();
            asm volatile("cp.async.wait_group 1;" ::: "memory");
        } else {
            asm volatile("cp.async.wait_group 0;" ::: "memory");
        }
        __syncthreads();
        g_kstep(smc + (ch & 1) * G2_STG, 0, wm, wn, acc);
        g_kstep(smc + (ch & 1) * G2_STG, 1, wm, wn, acc);
        __syncthreads();
    }

    float* Cs = (float*)smc;
#pragma unroll
    for (int i = 0; i < 4; ++i)
#pragma unroll
        for (int j = 0; j < 2; ++j)
            wmma::store_matrix_sync(&Cs[(wm + 16 * i) * 132 + wn + 16 * j],
                                    acc[i][j], 132, wmma::mem_row_major);
    __syncthreads();

    const int row = t >> 1, c0 = (t & 1) * 64;
    float* dst = out + (size_t)(m0 + row) * Dv + n0 + c0;
#pragma unroll
    for (int c = 0; c < 64; c += 4) {
        float4 v = *(float4*)&Cs[row * 132 + c0 + c];
        v.x += biasS[c0 + c + 0]; v.y += biasS[c0 + c + 1];
        v.z += biasS[c0 + c + 2]; v.w += biasS[c0 + c + 3];
        *(float4*)(dst + c) = v;
    }
}

// ===========================================================================
// Attention: SOFTWARE-PIPELINED. S(kt+1) fused with SV(kt) in one MMA phase.
// 256 thr, 8 warps x 16 q-rows; q-tile 128; KV 3-stage ring (1 block/SM).
// ===========================================================================
#define AT_Q    0
#define AT_KV   36864
#define AT_STG  36864
#define AT_PL   9216
#define ATTN_SMEM (36864 + 3 * 36864)   // 147456

__device__ __forceinline__ void kv_prefetch256(uint32_t dstbase, size_t hb,
                                               int row0, int t)
{
    const __nv_bfloat16* kvp[4] = {gk_hi + hb, gk_lo + hb, gv_hi + hb, gv_lo + hb};
#pragma unroll
    for (int hh = 0; hh < 8; ++hh) {
        const int o = t + 256 * hh;            // 0..2047
        const int plane = o >> 9;
        const int idx = o & 511;
        cp16(dstbase + plane * AT_PL + (idx >> 3) * 144 + (idx & 7) * 16,
             kvp[plane] + (size_t)(row0 + (idx >> 3)) * HDv + (idx & 7) * 8);
    }
}

// relu/scale/rowsum/split S -> bf16 hi/lo planes (registers)
__device__ __forceinline__ void splitS(const float (&s)[8][4],
                                       uint32_t (&sah)[4][4], uint32_t (&sal)[4][4],
                                       float& ds0, float& ds1)
{
#pragma unroll
    for (int kf = 0; kf < 4; ++kf) {
#pragma unroll
        for (int hh = 0; hh < 2; ++hh) {
            const float* c = s[2 * kf + hh];
            float c0 = fmaxf(c[0] * 0.125f, 0.f);
            float c1 = fmaxf(c[1] * 0.125f, 0.f);
            float c2 = fmaxf(c[2] * 0.125f, 0.f);
            float c3 = fmaxf(c[3] * 0.125f, 0.f);
            ds0 += c0 + c1;
            ds1 += c2 + c3;
            uint32_t h01 = cvt_bf2(c0, c1);
            uint32_t h23 = cvt_bf2(c2, c3);
            sah[kf][2 * hh + 0] = h01;
            sah[kf][2 * hh + 1] = h23;
            sal[kf][2 * hh + 0] = cvt_bf2(c0 - bflo_f(h01), c1 - bfhi_f(h01));
            sal[kf][2 * hh + 1] = cvt_bf2(c2 - bflo_f(h23), c3 - bfhi_f(h23));
        }
    }
}

// S(next) = Q . K(stK)^T   (prologue / standalone)
__device__ __forceinline__ void computeS(uint32_t stK, uint32_t qaddr, int kroff,
                                         float (&sn)[8][4])
{
#pragma unroll
    for (int i = 0; i < 8; ++i)
#pragma unroll
        for (int j = 0; j < 4; ++j) sn[i][j] = 0.f;
#pragma unroll
    for (int ks = 0; ks < 4; ++ks) {
        uint32_t aqh[4], aql[4];
        ldsm4(aqh, qaddr + ks * 32);
        ldsm4(aql, qaddr + 18432 + ks * 32);
#pragma unroll
        for (int np = 0; np < 4; ++np) {
            uint32_t bh[4], bl[4];
            ldsm4(bh, stK + np * 16 * 144 + kroff + ks * 32);
            ldsm4(bl, stK + AT_PL + np * 16 * 144 + kroff + ks * 32);
            mma16816(sn[2 * np],     aqh, bh[0], bh[1]);
            mma16816(sn[2 * np + 1], aqh, bh[2], bh[3]);
            mma16816(sn[2 * np],     aqh, bl[0], bl[1]);
            mma16816(sn[2 * np + 1], aqh, bl[2], bl[3]);
            mma16816(sn[2 * np],     aql, bh[0], bh[1]);
            mma16816(sn[2 * np + 1], aql, bh[2], bh[3]);
        }
    }
}

// Fused: SV(kt) [V from stV, S planes] + S(kt+1) [K from stK] -> sn
__device__ __forceinline__ void fusedStep(uint32_t stV, uint32_t stK,
                                          uint32_t qaddr, int kroff, int vroff,
                                          const uint32_t (&sah)[4][4],
                                          const uint32_t (&sal)[4][4],
                                          float (&ctx)[8][4], float (&sn)[8][4])
{
#pragma unroll
    for (int i = 0; i < 8; ++i)
#pragma unroll
        for (int j = 0; j < 4; ++j) sn[i][j] = 0.f;
#pragma unroll
    for (int u = 0; u < 4; ++u) {
        // --- S(kt+1), kstep u ---
        uint32_t aqh[4], aql[4];
        ldsm4(aqh, qaddr + u * 32);
        ldsm4(aql, qaddr + 18432 + u * 32);
#pragma unroll
        for (int np = 0; np < 4; ++np) {
            uint32_t bh[4], bl[4];
            ldsm4(bh, stK + np * 16 * 144 + kroff + u * 32);
            ldsm4(bl, stK + AT_PL + np * 16 * 144 + kroff + u * 32);
            mma16816(sn[2 * np],     aqh, bh[0], bh[1]);
            mma16816(sn[2 * np + 1], aqh, bh[2], bh[3]);
            mma16816(sn[2 * np],     aqh, bl[0], bl[1]);
            mma16816(sn[2 * np + 1], aqh, bl[2], bl[3]);
            mma16816(sn[2 * np],     aql, bh[0], bh[1]);
            mma16816(sn[2 * np + 1], aql, bh[2], bh[3]);
        }
        // --- SV(kt), kf = u ---
#pragma unroll
        for (int np = 0; np < 4; ++np) {
            uint32_t bvh[4], bvl[4];
            ldsm4t(bvh, stV + 2 * AT_PL + u * 16 * 144 + vroff + np * 32);
            ldsm4t(bvl, stV + 3 * AT_PL + u * 16 * 144 + vroff + np * 32);
            mma16816(ctx[2 * np],     sah[u], bvh[0], bvh[1]);
            mma16816(ctx[2 * np + 1], sah[u], bvh[2], bvh[3]);
            mma16816(ctx[2 * np],     sah[u], bvl[0], bvl[1]);
            mma16816(ctx[2 * np + 1], sah[u], bvl[2], bvl[3]);
            mma16816(ctx[2 * np],     sal[u], bvh[0], bvh[1]);
            mma16816(ctx[2 * np + 1], sal[u], bvh[2], bvh[3]);
        }
    }
}

__device__ __forceinline__ void svOnly(uint32_t stV, int vroff,
                                       const uint32_t (&sah)[4][4],
                                       const uint32_t (&sal)[4][4],
                                       float (&ctx)[8][4])
{
#pragma unroll
    for (int u = 0; u < 4; ++u)
#pragma unroll
        for (int np = 0; np < 4; ++np) {
            uint32_t bvh[4], bvl[4];
            ldsm4t(bvh, stV + 2 * AT_PL + u * 16 * 144 + vroff + np * 32);
            ldsm4t(bvl, stV + 3 * AT_PL + u * 16 * 144 + vroff + np * 32);
            mma16816(ctx[2 * np],     sah[u], bvh[0], bvh[1]);
            mma16816(ctx[2 * np + 1], sah[u], bvh[2], bvh[3]);
            mma16816(ctx[2 * np],     sah[u], bvl[0], bvl[1]);
            mma16816(ctx[2 * np + 1], sah[u], bvl[2], bvl[3]);
            mma16816(ctx[2 * np],     sal[u], bvh[0], bvh[1]);
            mma16816(ctx[2 * np + 1], sal[u], bvh[2], bvh[3]);
        }
}

__global__ __launch_bounds__(256, 1) void attn_m()
{
    extern __shared__ char smc[];
    const uint32_t sb = (uint32_t)__cvta_generic_to_shared(smc);
    const int t = threadIdx.x;
    const int l = t & 31;
    const int w = t >> 5;                      // 0..7
    const int qn0 = blockIdx.x * 128;
    const int tbh = blockIdx.y;
    const size_t hb = (size_t)tbh * Nv * HDv;

    // group0: Q planes + KV0; group1: KV1; group2: KV2
#pragma unroll
    for (int hh = 0; hh < 8; ++hh) {
        const int o = t + 256 * hh;            // 0..2047
        const int plane = o >> 10;
        const int idx = o & 1023;
        const __nv_bfloat16* src =
            (plane ? gq_lo : gq_hi) + hb + (size_t)(qn0 + (idx >> 3)) * HDv + (idx & 7) * 8;
        cp16(sb + AT_Q + plane * 18432 + (idx >> 3) * 144 + (idx & 7) * 16, src);
    }
    kv_prefetch256(sb + AT_KV, hb, 0, t);
    cp_commit();
    kv_prefetch256(sb + AT_KV + AT_STG, hb, 64, t);
    cp_commit();
    kv_prefetch256(sb + AT_KV + 2 * AT_STG, hb, 128, t);
    cp_commit();

    const uint32_t qaddr = sb + AT_Q + (w * 16 + (l & 15)) * 144 + (l >> 4) * 16;
    const int kroff = ((l & 7) + ((l >> 4) & 1) * 8) * 144 + ((l >> 3) & 1) * 16;
    const int vroff = ((l & 7) + ((l >> 3) & 1) * 8) * 144 + ((l >> 4) & 1) * 16;

    float ctx[8][4];
#pragma unroll
    for (int i = 0; i < 8; ++i)
#pragma unroll
        for (int j = 0; j < 4; ++j) ctx[i][j] = 0.f;
    float ds0 = 0.f, ds1 = 0.f;

    uint32_t stV = sb + AT_KV;                 // stage(kt)
    uint32_t stK = sb + AT_KV + AT_STG;        // stage(kt+1)
    const uint32_t stHi = sb + AT_KV + 2 * AT_STG;

    float sA[8][4], sB[8][4];
    uint32_t sah[4][4], sal[4][4];

    asm volatile("cp.async.wait_group 2;" ::: "memory");   // Q + KV0
    __syncthreads();
    computeS(stV, qaddr, kroff, sA);                        // S(0)

    for (int kt = 0; kt < 14; kt += 2) {
        // --- step A (tile kt, S in sA) ---
        splitS(sA, sah, sal, ds0, ds1);
        asm volatile("cp.async.wait_group 1;" ::: "memory");  // KV(kt+1) done
        __syncthreads();
        fusedStep(stV, stK, qaddr, kroff, vroff, sah, sal, ctx, sB);
        __syncthreads();
        kv_prefetch256(stV, hb, (kt + 3) * 64, t);            // KV(kt+3)
        cp_commit();
        { uint32_t tmp = stK; stK = (stK == stHi) ? sb + AT_KV : stK + AT_STG; stV = tmp; }

        // --- step B (tile kt+1, S in sB) ---
        splitS(sB, sah, sal, ds0, ds1);
        asm volatile("cp.async.wait_group 1;" ::: "memory");  // KV(kt+2) done
        __syncthreads();
        fusedStep(stV, stK, qaddr, kroff, vroff, sah, sal, ctx, sA);
        __syncthreads();
        if (kt + 4 <= 15) {
            kv_prefetch256(stV, hb, (kt + 4) * 64, t);        // KV(kt+4)
            cp_commit();
        }
        { uint32_t tmp = stK; stK = (stK == stHi) ? sb + AT_KV : stK + AT_STG; stV = tmp; }
    }

    // kt = 14: SV(14) + S(15)
    splitS(sA, sah, sal, ds0, ds1);
    asm volatile("cp.async.wait_group 0;" ::: "memory");      // KV(15) done
    __syncthreads();
    fusedStep(stV, stK, qaddr, kroff, vroff, sah, sal, ctx, sB);
    stV = stK;

    // kt = 15: SV only
    splitS(sB, sah, sal, ds0, ds1);
    svOnly(stV, vroff, sah, sal, ctx);

    // epilogue
    const int g = l >> 2, tg = l & 3;
    const int hd0 = (tbh & 7) * HDv;
    ds0 += __shfl_xor_sync(0xffffffffu, ds0, 1);
    ds0 += __shfl_xor_sync(0xffffffffu, ds0, 2);
    ds1 += __shfl_xor_sync(0xffffffffu, ds1, 1);
    ds1 += __shfl_xor_sync(0xffffffffu, ds1, 2);
    const float inv0 = 1.f / (ds0 + 1e-6f);
    const float inv1 = 1.f / (ds1 + 1e-6f);

    const int mtok = (tbh >> 3) * Nv + qn0 + w * 16 + g;
    __nv_bfloat16* dh0 = gc_hi + (size_t)mtok * Dv + hd0;
    __nv_bfloat16* dl0 = gc_lo + (size_t)mtok * Dv + hd0;
    __nv_bfloat16* dh1 = dh0 + 8 * Dv;
    __nv_bfloat16* dl1 = dl0 + 8 * Dv;
#pragma unroll
    for (int i = 0; i < 8; ++i) {
        const int d = (i >> 1) * 16 + (i & 1) * 8 + tg * 2;
        float v0 = ctx[i][0] * inv0, v1 = ctx[i][1] * inv0;
        float v2 = ctx[i][2] * inv1, v3 = ctx[i][3] * inv1;
        uint32_t h01 = cvt_bf2(v0, v1);
        uint32_t h23 = cvt_bf2(v2, v3);
        *(uint32_t*)(dh0 + d) = h01;
        *(uint32_t*)(dl0 + d) = cvt_bf2(v0 - bflo_f(h01), v1 - bfhi_f(h01));
        *(uint32_t*)(dh1 + d) = h23;
        *(uint32_t*)(dl1 + d) = cvt_bf2(v2 - bflo_f(h23), v3 - bfhi_f(h23));
    }
}

// ---------------------------------------------------------------------------
extern "C" void kernel_launch(void* const* d_in, const int* in_sizes, int n_in,
                              void* d_out, int out_size)
{
    const float* x  = (const float*)d_in[0];
    const float* wq = (const float*)d_in[1];
    const float* bq = (const float*)d_in[2];
    const float* wk = (const float*)d_in[3];
    const float* bk = (const float*)d_in[4];
    const float* wv = (const float*)d_in[5];
    const float* bv = (const float*)d_in[6];
    const float* wo = (const float*)d_in[7];
    const float* bo = (const float*)d_in[8];
    float* out = (float*)d_out;

    cudaFuncSetAttribute(qkv_gemm_p, cudaFuncAttributeMaxDynamicSharedMemorySize, GEMM_SMEM);
    cudaFuncSetAttribute(out_gemm_p, cudaFuncAttributeMaxDynamicSharedMemorySize, GEMM2_SMEM);
    cudaFuncSetAttribute(attn_m, cudaFuncAttributeMaxDynamicSharedMemorySize, ATTN_SMEM);

    const int splitBlocks = (NXf4 + 4 * NWf4 + 255) / 256;
    split_kernel<<<splitBlocks, 256>>>(x, wq, wk, wv, wo);
    qkv_gemm_p<<<dim3(Mv / 128, 12), 256, GEMM_SMEM>>>(bq, bk, bv);
    attn_m<<<dim3(Nv / 128, TBv * Hv), 256, ATTN_SMEM>>>();
    out_gemm_p<<<dim3(Mv / 128, Dv / 128), 256, GEMM2_SMEM>>>(bo, out);
}